// round 13
// baseline (speedup 1.0000x reference)
#include <cuda_runtime.h>
#include <cuda_fp16.h>
#include <cstdint>

#define SCALE_ 0.03125f   // 1/sqrt(1024)

// ---------------- fp16-split scratch (device globals; no allocation) -------
__device__ __half g_Xhi[8192*1024];
__device__ __half g_Xlo[8192*1024];
__device__ __half g_Wqhi[1024*1024];
__device__ __half g_Wqlo[1024*1024];
__device__ __half g_Wkhi[1024*1024];
__device__ __half g_Wklo[1024*1024];
__device__ __half g_Wvhi[1024*1024];
__device__ __half g_Wvlo[1024*1024];
__device__ __half g_Qhi[8192*1024];          // Q: hi only (A operand)
__device__ __half g_Khi[8192*1024];
__device__ __half g_Klo[8192*1024];
__device__ __half g_Vthi[1024*8192];          // V^T hi: [C, B*N]
__device__ __half g_AThi[16777216];           // attention hi [B,N,N] (A operand)

// ---------------- stream/event infra (created at load, before checkpoints) -
static cudaStream_t gsK, gsV, gs3;   // zero-init -> default stream fallback
static cudaEvent_t  geFork, geX, geQ, geK, geV, geWq, geB1, geB2, geB3;
namespace {
struct StreamInit {
    StreamInit() {
        cudaStreamCreateWithFlags(&gsK, cudaStreamNonBlocking);
        cudaStreamCreateWithFlags(&gsV, cudaStreamNonBlocking);
        cudaStreamCreateWithFlags(&gs3, cudaStreamNonBlocking);
        cudaEventCreateWithFlags(&geFork, cudaEventDisableTiming);
        cudaEventCreateWithFlags(&geX, cudaEventDisableTiming);
        cudaEventCreateWithFlags(&geQ, cudaEventDisableTiming);
        cudaEventCreateWithFlags(&geK, cudaEventDisableTiming);
        cudaEventCreateWithFlags(&geV, cudaEventDisableTiming);
        cudaEventCreateWithFlags(&geWq, cudaEventDisableTiming);
        cudaEventCreateWithFlags(&geB1, cudaEventDisableTiming);
        cudaEventCreateWithFlags(&geB2, cudaEventDisableTiming);
        cudaEventCreateWithFlags(&geB3, cudaEventDisableTiming);
    }
};
static StreamInit g_si;
}

// ---------------- PTX helpers ----------------------------------------------
__device__ __forceinline__ uint32_t smem_u32(const void* p) {
    uint32_t a;
    asm("{ .reg .u64 t; cvta.to.shared.u64 t, %1; cvt.u32.u64 %0, t; }"
        : "=r"(a) : "l"(p));
    return a;
}

__device__ __forceinline__ void cpa16(uint32_t dst, const void* src) {
    asm volatile("cp.async.cg.shared.global [%0], [%1], 16;" :: "r"(dst), "l"(src));
}
#define CP_COMMIT() asm volatile("cp.async.commit_group;" ::: "memory")

__device__ __forceinline__ void ldm4(uint32_t* r, uint32_t a) {
    asm volatile("ldmatrix.sync.aligned.m8n8.x4.shared.b16 {%0,%1,%2,%3}, [%4];"
        : "=r"(r[0]), "=r"(r[1]), "=r"(r[2]), "=r"(r[3]) : "r"(a));
}

__device__ __forceinline__ void mma16816(float* d, const uint32_t* a,
                                         uint32_t b0, uint32_t b1) {
    asm volatile(
        "mma.sync.aligned.m16n8k16.row.col.f32.f16.f16.f32 "
        "{%0,%1,%2,%3}, {%4,%5,%6,%7}, {%8,%9}, {%0,%1,%2,%3};"
        : "+f"(d[0]), "+f"(d[1]), "+f"(d[2]), "+f"(d[3])
        : "r"(a[0]), "r"(a[1]), "r"(a[2]), "r"(a[3]), "r"(b0), "r"(b1));
}

// ---------------- GEMM kernel ----------------------------------------------
// C[m,n] = sum_k A[m,k]*B[n,k]  (NT, fp16 split).
// NPASS=2: acc = Ah*Bh + Ah*Bl.  NPASS=1: acc = Ah*Bh.
// CTA tile 128x128, BK=32, 4 warps (64x64), 3-stage cp.async, 2 CTAs/SM.
// MODE 0: out = acc + bias[n] -> fp16 hi (+lo if outLo)
// MODE 1: out = acc + bias[m] -> fp16 hi (+lo if outLo)
// MODE 2/3: out = acc * scale -> fp32
#define BM 128
#define BN 128
#define BKt 32
#define TILE_STRIDE 80                 // bytes per 32-elem fp16 row (+16B pad)
#define SUB_BYTES (128*TILE_STRIDE)    // 10240
#define SMEM_P2 (3*3*SUB_BYTES)        // 92160 (Ah Bh Bl x 3 stages)
#define SMEM_P1 (3*2*SUB_BYTES)        // 61440 (Ah Bh    x 3 stages)

template<int NPASS>
__device__ __forceinline__ void load_tile(
    uint32_t stbase,
    const __half* pAh, const __half* pBh, const __half* pBl,
    long long ldA, long long ldB, int k0, int tid)
{
#pragma unroll
    for (int t = 0; t < 4; t++) {
        int id = tid + t * 128;
        int r = id >> 2, c = id & 3;
        uint32_t doff = (uint32_t)r * TILE_STRIDE + c * 16;
        long long soA = (long long)r * ldA + k0 + c * 8;
        long long soB = (long long)r * ldB + k0 + c * 8;
        cpa16(stbase + doff,               pAh + soA);
        cpa16(stbase + SUB_BYTES + doff,   pBh + soB);
        if (NPASS == 2) cpa16(stbase + 2*SUB_BYTES + doff, pBl + soB);
    }
}

template<int MODE, int NPASS>
__global__ __launch_bounds__(128, 2) void mm_kernel(
    const __half* __restrict__ Ah, long long ldA, long long strideA,
    const __half* __restrict__ Bh, const __half* __restrict__ Bl,
    long long ldB, long long strideB,
    const float* __restrict__ bias,
    float* __restrict__ outF,
    __half* __restrict__ outHi, __half* __restrict__ outLo,
    long long ldC, long long strideC,
    int Ksz, float scale)
{
    constexpr uint32_t STB = (uint32_t)((1 + NPASS) * SUB_BYTES);
    extern __shared__ char smem[];
    const uint32_t sb = smem_u32(smem);
    const int tid = threadIdx.x;
    const int wid = tid >> 5, lane = tid & 31;
    const int wm = wid >> 1, wn = wid & 1;        // 2 x 2 warp grid, 64x64 tiles
    const int g8 = lane & 7, quad = lane >> 3;
    const int g = lane >> 2, tg = lane & 3;

    const long long bz = blockIdx.z;
    const long long tileM = (long long)blockIdx.y * BM;
    const long long tileN = (long long)blockIdx.x * BN;
    const __half* pAh = Ah + bz * strideA + tileM * ldA;
    const __half* pBh = Bh + bz * strideB + tileN * ldB;
    const __half* pBl = (NPASS == 2) ? (Bl + bz * strideB + tileN * ldB) : nullptr;

    float acc[4][8][4];
#pragma unroll
    for (int i = 0; i < 4; i++)
#pragma unroll
        for (int j = 0; j < 8; j++)
#pragma unroll
            for (int c = 0; c < 4; c++) acc[i][j][c] = 0.f;

    const int KT = Ksz / BKt;

    // prologue: 2 of 3 stages in flight
    load_tile<NPASS>(sb + 0*STB, pAh, pBh, pBl, ldA, ldB, 0, tid);
    CP_COMMIT();
    load_tile<NPASS>(sb + 1*STB, pAh, pBh, pBl, ldA, ldB, BKt, tid);
    CP_COMMIT();

    const uint32_t aBase = (uint32_t)(wm*64 + g8 + ((quad & 1) ? 8 : 0)) * TILE_STRIDE
                         + ((quad & 2) ? 16 : 0);
    const uint32_t bBase = (uint32_t)(wn*64 + g8 + ((quad & 2) ? 8 : 0)) * TILE_STRIDE
                         + ((quad & 1) ? 16 : 0);

    int stageC = 0;
#pragma unroll 1
    for (int kt = 0; kt < KT; kt++) {
        if (kt < KT - 1) asm volatile("cp.async.wait_group 1;" ::: "memory");
        else             asm volatile("cp.async.wait_group 0;" ::: "memory");
        __syncthreads();
        const uint32_t base = sb + stageC * STB;
        if (kt + 2 < KT) {
            int stageN = stageC + 2; if (stageN >= 3) stageN -= 3;
            load_tile<NPASS>(sb + stageN * STB, pAh, pBh, pBl,
                             ldA, ldB, (kt + 2) * BKt, tid);
            CP_COMMIT();
        }
#pragma unroll
        for (int ks = 0; ks < 2; ks++) {
            uint32_t ah[4][4], bb[4][4];
#pragma unroll
            for (int i = 0; i < 4; i++)
                ldm4(ah[i], base + aBase + i * (16*TILE_STRIDE) + ks * 32);
            // pass 1: Ah * Bh
#pragma unroll
            for (int j = 0; j < 4; j++)
                ldm4(bb[j], base + SUB_BYTES + bBase + j * (16*TILE_STRIDE) + ks * 32);
#pragma unroll
            for (int i = 0; i < 4; i++)
#pragma unroll
                for (int j = 0; j < 8; j++)
                    mma16816(acc[i][j], ah[i], bb[j>>1][(j&1)*2], bb[j>>1][(j&1)*2+1]);
            if (NPASS == 2) {
                // pass 2: Ah * Bl
#pragma unroll
                for (int j = 0; j < 4; j++)
                    ldm4(bb[j], base + 2*SUB_BYTES + bBase + j * (16*TILE_STRIDE) + ks * 32);
#pragma unroll
                for (int i = 0; i < 4; i++)
#pragma unroll
                    for (int j = 0; j < 8; j++)
                        mma16816(acc[i][j], ah[i], bb[j>>1][(j&1)*2], bb[j>>1][(j&1)*2+1]);
            }
        }
        if (++stageC == 3) stageC = 0;
    }

    // ---------------- epilogue ----------------
    const long long rowBase = tileM + wm * 64;
    const long long colBase = tileN + wn * 64;
    const long long cOff = bz * strideC;
#pragma unroll
    for (int i = 0; i < 4; i++) {
#pragma unroll
        for (int j = 0; j < 8; j++) {
            long long r0 = rowBase + i * 16 + g;
            long long c0 = colBase + j * 8 + 2 * tg;
#pragma unroll
            for (int h = 0; h < 2; h++) {
                long long r = r0 + h * 8;
                float f0 = acc[i][j][2*h + 0];
                float f1 = acc[i][j][2*h + 1];
                long long off = cOff + r * ldC + c0;
                if (MODE >= 2) {
                    float2 v; v.x = f0 * scale; v.y = f1 * scale;
                    *(float2*)(outF + off) = v;
                } else {
                    if (MODE == 0) { f0 += bias[c0]; f1 += bias[c0 + 1]; }
                    else           { float bb2 = bias[r]; f0 += bb2; f1 += bb2; }
                    __half h0 = __float2half_rn(f0);
                    __half h1 = __float2half_rn(f1);
                    uint32_t hp = (uint32_t)__half_as_ushort(h0) |
                                  ((uint32_t)__half_as_ushort(h1) << 16);
                    *(uint32_t*)(outHi + off) = hp;
                    if (outLo) {
                        __half l0 = __float2half_rn(f0 - __half2float(h0));
                        __half l1 = __float2half_rn(f1 - __half2float(h1));
                        uint32_t lp = (uint32_t)__half_as_ushort(l0) |
                                      ((uint32_t)__half_as_ushort(l1) << 16);
                        *(uint32_t*)(outLo + off) = lp;
                    }
                }
            }
        }
    }
}

// ---------------- split fp32 -> fp16 hi/lo (4 float4 per thread, ILP) ------
__global__ __launch_bounds__(256) void split_kernel(
    const float4* __restrict__ src, uint2* __restrict__ hi, uint2* __restrict__ lo, int n4)
{
    int i0 = blockIdx.x * 1024 + threadIdx.x;
    float4 v[4];
    int idx[4];
#pragma unroll
    for (int t = 0; t < 4; t++) {
        idx[t] = i0 + t * 256;
        if (idx[t] < n4) v[t] = src[idx[t]];
    }
#pragma unroll
    for (int t = 0; t < 4; t++) {
        if (idx[t] >= n4) continue;
        float f[4] = {v[t].x, v[t].y, v[t].z, v[t].w};
        uint32_t hh[2], ll[2];
#pragma unroll
        for (int j = 0; j < 2; j++) {
            __half h0 = __float2half_rn(f[2*j]);
            __half h1 = __float2half_rn(f[2*j+1]);
            __half l0 = __float2half_rn(f[2*j]   - __half2float(h0));
            __half l1 = __float2half_rn(f[2*j+1] - __half2float(h1));
            hh[j] = (uint32_t)__half_as_ushort(h0) | ((uint32_t)__half_as_ushort(h1) << 16);
            ll[j] = (uint32_t)__half_as_ushort(l0) | ((uint32_t)__half_as_ushort(l1) << 16);
        }
        hi[idx[t]] = make_uint2(hh[0], hh[1]);
        lo[idx[t]] = make_uint2(ll[0], ll[1]);
    }
}

// ---------------- softmax rows, in-place, + fp16 hi ------------------------
__global__ __launch_bounds__(256) void softmax_split_kernel(
    float* __restrict__ att, __half* __restrict__ ahi)
{
    __shared__ float row[2048];
    __shared__ float red[8];
    const long long base = (long long)blockIdx.x * 2048;
    float* p = att + base;
    const int tid = threadIdx.x;

    float m = -3.0e38f;
    for (int i = tid; i < 2048; i += 256) { float v = p[i]; row[i] = v; m = fmaxf(m, v); }
#pragma unroll
    for (int o = 16; o > 0; o >>= 1) m = fmaxf(m, __shfl_xor_sync(0xffffffffu, m, o));
    if ((tid & 31) == 0) red[tid >> 5] = m;
    __syncthreads();
    m = red[0];
#pragma unroll
    for (int i = 1; i < 8; i++) m = fmaxf(m, red[i]);
    __syncthreads();

    float s = 0.f;
    for (int i = tid; i < 2048; i += 256) { float e = __expf(row[i] - m); row[i] = e; s += e; }
#pragma unroll
    for (int o = 16; o > 0; o >>= 1) s += __shfl_xor_sync(0xffffffffu, s, o);
    if ((tid & 31) == 0) red[tid >> 5] = s;
    __syncthreads();
    s = red[0];
#pragma unroll
    for (int i = 1; i < 8; i++) s += red[i];
    const float inv = 1.f / s;

    for (int i = tid; i < 2048; i += 256) {
        float v = row[i] * inv;
        p[i] = v;
        ahi[base + i] = __float2half_rn(v);
    }
}

// ---------------------------------------------------------------------------
extern "C" void kernel_launch(void* const* d_in, const int* in_sizes, int n_in,
                              void* d_out, int out_size)
{
    const float* X  = (const float*)d_in[0];
    const float* Wq = (const float*)d_in[1];
    const float* bq = (const float*)d_in[2];
    const float* Wk = (const float*)d_in[3];
    const float* bk = (const float*)d_in[4];
    const float* Wv = (const float*)d_in[5];
    const float* bv = (const float*)d_in[6];

    float* outp = (float*)d_out;                      // [4,2048,1024]
    float* att  = outp + 8388608ll;                   // [4,2048,2048]

    __half *Xhi, *Xlo, *Wqh, *Wql, *Wkh, *Wkl, *Wvh, *Wvl;
    __half *Qhi, *Khi, *Klo, *Vth, *Ahi;
    cudaGetSymbolAddress((void**)&Xhi, g_Xhi);  cudaGetSymbolAddress((void**)&Xlo, g_Xlo);
    cudaGetSymbolAddress((void**)&Wqh, g_Wqhi); cudaGetSymbolAddress((void**)&Wql, g_Wqlo);
    cudaGetSymbolAddress((void**)&Wkh, g_Wkhi); cudaGetSymbolAddress((void**)&Wkl, g_Wklo);
    cudaGetSymbolAddress((void**)&Wvh, g_Wvhi); cudaGetSymbolAddress((void**)&Wvl, g_Wvlo);
    cudaGetSymbolAddress((void**)&Qhi, g_Qhi);
    cudaGetSymbolAddress((void**)&Khi, g_Khi);  cudaGetSymbolAddress((void**)&Klo, g_Klo);
    cudaGetSymbolAddress((void**)&Vth, g_Vthi);
    cudaGetSymbolAddress((void**)&Ahi, g_AThi);

    cudaFuncSetAttribute((const void*)mm_kernel<0,2>, cudaFuncAttributeMaxDynamicSharedMemorySize, SMEM_P2);
    cudaFuncSetAttribute((const void*)mm_kernel<1,2>, cudaFuncAttributeMaxDynamicSharedMemorySize, SMEM_P2);
    cudaFuncSetAttribute((const void*)mm_kernel<2,2>, cudaFuncAttributeMaxDynamicSharedMemorySize, SMEM_P2);
    cudaFuncSetAttribute((const void*)mm_kernel<3,1>, cudaFuncAttributeMaxDynamicSharedMemorySize, SMEM_P1);

    const cudaStream_t s0 = 0;
    const cudaStream_t sK = gsK;   // zero-init fallback = default stream (serial, correct)
    const cudaStream_t sV = gsV;
    const cudaStream_t s3 = gs3;
    cudaStream_t chainS[4] = {s0, sK, sV, s3};

    const long long sQK  = 2097152ll;   // per-batch Q/K/out elements
    const long long sNN  = 4194304ll;   // per-batch att elements
    const long long hQK  = 1048576ll;   // half-batch (1024 rows) Q/out elements
    const long long hNN  = 2097152ll;   // half-batch att elements

    // ---- fork point: side streams must first wait on an event recorded in
    //      the capture-origin stream before ANY work lands on them ----
    cudaEventRecord(geFork, s0);
    cudaStreamWaitEvent(sK, geFork, 0);
    cudaStreamWaitEvent(sV, geFork, 0);
    cudaStreamWaitEvent(s3, geFork, 0);

    // ---- W splits on forked streams (no X dependency; overlap X split) ----
    split_kernel<<<256, 256, 0, sK>>>((const float4*)Wk, (uint2*)Wkh, (uint2*)Wkl, 262144);
    split_kernel<<<256, 256, 0, sV>>>((const float4*)Wv, (uint2*)Wvh, (uint2*)Wvl, 262144);
    split_kernel<<<256, 256, 0, s3>>>((const float4*)Wq, (uint2*)Wqh, (uint2*)Wql, 262144);
    cudaEventRecord(geWq, s3);

    // ---- X split on main stream ----
    split_kernel<<<2048, 256, 0, s0>>>((const float4*)X, (uint2*)Xhi, (uint2*)Xlo, 2097152);
    cudaEventRecord(geX, s0);

    // ---- branch K: Kproj ----
    cudaStreamWaitEvent(sK, geX, 0);
    mm_kernel<0,2><<<dim3(8, 64, 1), 128, SMEM_P2, sK>>>(
        Xhi, 1024, 0, Wkh, Wkl, 1024, 0, bk,
        nullptr, Khi, Klo, 1024, 0, 1024, 1.f);
    cudaEventRecord(geK, sK);

    // ---- branch V: Vproj (V^T = Wv X^T + bv(row)) ----
    cudaStreamWaitEvent(sV, geX, 0);
    mm_kernel<1,2><<<dim3(64, 8, 1), 128, SMEM_P2, sV>>>(
        Wvh, 1024, 0, Xhi, Xlo, 1024, 0, bv,
        nullptr, Vth, nullptr, 8192, 0, 1024, 1.f);
    cudaEventRecord(geV, sV);

    // ---- main stream: Q proj (after X split on s0 and Wq split on s3) ----
    cudaStreamWaitEvent(s0, geWq, 0);
    mm_kernel<0,2><<<dim3(8, 64, 1), 128, SMEM_P2, s0>>>(
        Xhi, 1024, 0, Wqh, Wql, 1024, 0, bq,
        nullptr, Qhi, nullptr, 1024, 0, 1024, 1.f);
    cudaEventRecord(geQ, s0);

    // ---- 8 half-batch chains: scores(b,h) -> softmax(b,h) -> AV(b,h) ----
    for (int c = 0; c < 8; c++) {
        const int b = c >> 1, h = c & 1;
        cudaStream_t st = chainS[c & 3];
        cudaStreamWaitEvent(st, geQ, 0);
        cudaStreamWaitEvent(st, geK, 0);
        const __half* qrow = Qhi + b * sQK + (long long)h * hQK;       // 1024 rows
        float*        arow = att + b * sNN + (long long)h * hNN;
        __half*       hrow = Ahi + b * sNN + (long long)h * hNN;
        // scores: M=1024 (half), N=2048, K=1024
        mm_kernel<2,2><<<dim3(16, 8, 1), 128, SMEM_P2, st>>>(
            qrow, 1024, 0, Khi + b * sQK, Klo + b * sQK, 1024, 0, nullptr,
            arow, nullptr, nullptr, 2048, 0, 1024, SCALE_);
        // softmax on 1024 rows
        softmax_split_kernel<<<1024, 256, 0, st>>>(arow, hrow);
        // AV: M=1024 (half), N=1024, K=2048
        cudaStreamWaitEvent(st, geV, 0);
        mm_kernel<3,1><<<dim3(8, 8, 1), 128, SMEM_P1, st>>>(
            hrow, 2048, 0, Vth + b * 2048, nullptr, 8192, 0, nullptr,
            outp + b * sQK + (long long)h * hQK, nullptr, nullptr, 1024, 0, 2048, 1.f);
    }

    // ---- join all side streams back into the origin stream ----
    cudaEventRecord(geB1, sK);
    cudaEventRecord(geB2, sV);
    cudaEventRecord(geB3, s3);
    cudaStreamWaitEvent(s0, geB1, 0);
    cudaStreamWaitEvent(s0, geB2, 0);
    cudaStreamWaitEvent(s0, geB3, 0);
}